// round 17
// baseline (speedup 1.0000x reference)
#include <cuda_runtime.h>

// query [32, 2048] f32, W [2048, 100] f32, out [32, 100] f32.
// out[b,o] = sum_j (q - (2048*trunc(q) + S[b]))^2 W[j,o],  S[b] = sum_j trunc(q[b,j]).
// Expansion: d0 = q - 2048*trunc(q)  (local, no S needed)
//   out[b,o] = P2[b,o] - 2 S[b] P1[b,o] + S[b]^2 Wbar[o]
//   P1 = sum d0*W, P2 = sum d0^2*W, Wbar = sum W.  Single kernel, ticket combine.

#define BATCH   32
#define NDIM    2048
#define NOUT    100
#define KSPLIT  16
#define KCHUNK  (NDIM / KSPLIT)      // 128
#define NT      512
#define NW      (NT / 32)            // 16 warps
#define JW      (KCHUNK / NW)        // 8 j's per warp
#define NBLOCKS (BATCH * KSPLIT)     // 512

__device__ float        g_P1[BATCH * NOUT];   // zero-init (.bss), re-zeroed per run
__device__ float        g_P2[BATCH * NOUT];
__device__ float        g_Wbar[NOUT];
__device__ int          g_Ssum[BATCH];
__device__ unsigned int g_done;

__global__ __launch_bounds__(NT)
void fused_single(const float* __restrict__ q,
                  const float* __restrict__ W,
                  float* __restrict__ out) {
    const int b     = blockIdx.x;        // 0..31
    const int kbase = blockIdx.y * KCHUNK;

    __shared__ float d0s[KCHUNK];
    __shared__ float part1[NW][25][4];
    __shared__ float part2[NW][25][4];
    __shared__ float partw[NW][25][4];
    __shared__ bool  is_last;

    const int tid  = threadIdx.x;
    const int lane = tid & 31;
    const int wrp  = tid >> 5;

    // ---- d0 for this chunk + partial S (warps 0..3 fully active) ----
    if (tid < KCHUNK) {
        const float v = q[b * NDIM + kbase + tid];
        const int   c = (int)v;                     // trunc == astype(int32)
        d0s[tid] = v - 2048.0f * (float)c;          // exact (|2048c| < 2^24)
        const int s = __reduce_add_sync(0xffffffffu, c);
        if (lane == 0) atomicAdd(&g_Ssum[b], s);
    }
    __syncthreads();

    // ---- P1/P2/Wbar partials: warp -> 8-j slice, lane<25 -> col quad ----
    if (lane < 25) {
        float a1x=0.f,a1y=0.f,a1z=0.f,a1w=0.f;
        float a2x=0.f,a2y=0.f,a2z=0.f,a2w=0.f;
        float awx=0.f,awy=0.f,awz=0.f,aww=0.f;
        const float4* W4 = (const float4*)W;        // row = 25 float4 (400B, aligned)
        const int j0 = wrp * JW;
        #pragma unroll
        for (int i = 0; i < JW; i++) {
            const int j = j0 + i;
            const float4 w = __ldg(&W4[(kbase + j) * 25 + lane]);
            const float d  = d0s[j];
            const float ds = d * d;
            a1x = fmaf(d,  w.x, a1x); a1y = fmaf(d,  w.y, a1y);
            a1z = fmaf(d,  w.z, a1z); a1w = fmaf(d,  w.w, a1w);
            a2x = fmaf(ds, w.x, a2x); a2y = fmaf(ds, w.y, a2y);
            a2z = fmaf(ds, w.z, a2z); a2w = fmaf(ds, w.w, a2w);
            awx += w.x; awy += w.y; awz += w.z; aww += w.w;
        }
        part1[wrp][lane][0]=a1x; part1[wrp][lane][1]=a1y; part1[wrp][lane][2]=a1z; part1[wrp][lane][3]=a1w;
        part2[wrp][lane][0]=a2x; part2[wrp][lane][1]=a2y; part2[wrp][lane][2]=a2z; part2[wrp][lane][3]=a2w;
        partw[wrp][lane][0]=awx; partw[wrp][lane][1]=awy; partw[wrp][lane][2]=awz; partw[wrp][lane][3]=aww;
    }
    __syncthreads();

    // ---- Fold 16 warp partials, spread atomics into scratch ----
    if (tid < 200) {                                 // P1 (even) / P2 (odd) per col
        const int which = tid & 1;
        const int col   = tid >> 1;                  // 0..99
        const int l = col >> 2, cc = col & 3;
        float r = 0.f;
        if (which == 0) {
            #pragma unroll
            for (int p = 0; p < NW; p++) r += part1[p][l][cc];
            atomicAdd(&g_P1[b * NOUT + col], r);
        } else {
            #pragma unroll
            for (int p = 0; p < NW; p++) r += part2[p][l][cc];
            atomicAdd(&g_P2[b * NOUT + col], r);
        }
    } else if (b == 0 && tid >= 256 && tid < 356) {  // Wbar: only b==0 blocks
        const int col = tid - 256;
        const int l = col >> 2, cc = col & 3;
        float r = 0.f;
        #pragma unroll
        for (int p = 0; p < NW; p++) r += partw[p][l][cc];
        atomicAdd(&g_Wbar[col], r);
    }

    // ---- Ticket: every thread fences its own outstanding REDs first ----
    __threadfence();
    __syncthreads();
    if (tid == 0) {
        const unsigned int old = atomicAdd(&g_done, 1u);
        is_last = (old == NBLOCKS - 1);
    }
    __syncthreads();

    // ---- Last block: combine + write out + re-zero scratch ----
    if (is_last) {
        __threadfence();                             // acquire side
        for (int idx = tid; idx < BATCH * NOUT; idx += NT) {
            const int bb = idx / NOUT;
            const int oo = idx - bb * NOUT;
            const float p1 = __ldcg(&g_P1[idx]);
            const float p2 = __ldcg(&g_P2[idx]);
            const float wb = __ldcg(&g_Wbar[oo]);
            const float Sf = (float)__ldcg(&g_Ssum[bb]);
            out[idx] = fmaf(Sf * Sf, wb, fmaf(-2.0f * Sf, p1, p2));
        }
        // reset scratch for the next (deterministic) replay
        for (int idx = tid; idx < BATCH * NOUT; idx += NT) {
            g_P1[idx] = 0.f;
            g_P2[idx] = 0.f;
        }
        if (tid < NOUT)  g_Wbar[tid] = 0.f;
        if (tid < BATCH) g_Ssum[tid] = 0;
        __syncthreads();
        if (tid == 0) g_done = 0u;
    }
}

extern "C" void kernel_launch(void* const* d_in, const int* in_sizes, int n_in,
                              void* d_out, int out_size) {
    const float* q = (const float*)d_in[0];   // [32, 2048]
    const float* W = (const float*)d_in[1];   // [2048, 100]
    float* out = (float*)d_out;               // [32, 100]
    (void)in_sizes; (void)n_in; (void)out_size;

    dim3 grid(BATCH, KSPLIT);
    fused_single<<<grid, NT>>>(q, W, out);
}